// round 12
// baseline (speedup 1.0000x reference)
#include <cuda_runtime.h>
#include <math.h>
#include <stdint.h>

namespace {
constexpr int B_   = 256;
constexpr int L_   = 256;
constexpr int C_   = 128;
constexpr int HID_ = 128;
constexpr int H_   = 4;
constexpr int D_   = 32;
constexpr int E_   = 4096;
constexpr int EG_  = E_ + C_;     // 4224 edges per graph incl. self loops

constexpr int THREADS = 1024;

constexpr int HS = 132;           // row stride (floats); 132 % 32 == 4 -> conflict-free frags
constexpr int TS = 132;           // row stride for GEMM k-tiles

constexpr int SM_H   = 0;                 // h  : 128 x 132
constexpr int SM_XL  = 128 * HS;          // xl : 128 x 132
constexpr int SM_XR  = 2 * 128 * HS;      // xr : 128 x 132
constexpr int SM_T0  = 3 * 128 * HS;      // tile buffer 0 (16 x 132)
constexpr int SM_T1  = SM_T0 + 16 * TS;   // tile buffer 1 (16 x 132)
constexpr int SM_FLOATS = SM_T0 + 2 * 16 * TS;

constexpr int SMEM_BYTES = SM_FLOATS * 4  // float region
                         + 132 * 4        // rowptr
                         + 256 * 4        // att cache
                         + EG_ * 2        // srcs (u16)
                         + 64;            // pad
}

__device__ int            g_rowptr[C_ + 1];
__device__ unsigned short g_srcs[EG_];

// ---------------------------------------------------------------------------
// tf32 mma.sync helpers (baseline PTX, no sm_103a feature target needed)
// ---------------------------------------------------------------------------
__device__ __forceinline__ uint32_t cvt_tf32(float f) {
    uint32_t r;
    asm("cvt.rna.tf32.f32 %0, %1;" : "=r"(r) : "f"(f));
    return r;
}
__device__ __forceinline__ void split_tf32(float f, uint32_t& hi, uint32_t& lo) {
    hi = cvt_tf32(f);
    lo = cvt_tf32(f - __uint_as_float(hi));
}
__device__ __forceinline__ void mma8(float* c,
                                     const uint32_t* a,
                                     uint32_t b0, uint32_t b1) {
    asm volatile(
        "mma.sync.aligned.m16n8k8.row.col.f32.tf32.tf32.f32 "
        "{%0,%1,%2,%3}, {%4,%5,%6,%7}, {%8,%9}, {%0,%1,%2,%3};"
        : "+f"(c[0]), "+f"(c[1]), "+f"(c[2]), "+f"(c[3])
        : "r"(a[0]), "r"(a[1]), "r"(a[2]), "r"(a[3]), "r"(b0), "r"(b1));
}

// ---------------------------------------------------------------------------
// Preprocessing: detect int32 vs int64 edge_index, build dst-sorted CSR.
// ---------------------------------------------------------------------------
__global__ void prep_kernel(const int* __restrict__ ei) {
    __shared__ int deg[C_];
    __shared__ int cur[C_];
    __shared__ int s_is64;
    int tid = threadIdx.x;
    if (tid == 0) s_is64 = 1;
    __syncthreads();
    int bad = 0;
    for (int i = tid; i < E_; i += blockDim.x)
        if (ei[2 * i + 1] != 0) bad = 1;
    if (bad) s_is64 = 0;
    __syncthreads();
    const int is64 = s_is64;

    for (int i = tid; i < C_; i += blockDim.x) deg[i] = 1;  // self loop
    __syncthreads();
    for (int e = tid; e < E_; e += blockDim.x) {
        int dst = is64 ? ei[2 * E_ + 2 * e] : ei[E_ + e];
        atomicAdd(&deg[dst], 1);
    }
    __syncthreads();
    if (tid == 0) {
        int acc = 0;
        for (int n = 0; n < C_; n++) { g_rowptr[n] = acc; cur[n] = acc; acc += deg[n]; }
        g_rowptr[C_] = acc;
    }
    __syncthreads();
    for (int e = tid; e < E_; e += blockDim.x) {
        int src = is64 ? ei[2 * e] : ei[e];
        int dst = is64 ? ei[2 * E_ + 2 * e] : ei[E_ + e];
        int p = atomicAdd(&cur[dst], 1);
        g_srcs[p] = (unsigned short)src;
    }
    __syncthreads();
    for (int n = tid; n < C_; n += blockDim.x) {
        int p = atomicAdd(&cur[n], 1);
        g_srcs[p] = (unsigned short)n;
    }
}

__device__ __forceinline__ float warpSum(float v) {
    #pragma unroll
    for (int o = 16; o > 0; o >>= 1) v += __shfl_xor_sync(0xFFFFFFFFu, v, o);
    return v;
}

// ---------------------------------------------------------------------------
// Main kernel: one CTA (1024 threads) per batch.
// GEMMs: warp-level tf32 mma.sync, 3-pass tf32 split, fragments read directly
// from fp32 smem. 32 warps = 8 rowgroups (m16) x 4 colgroups (n32).
// Edge phase: lane covers dims 4*lane..+3 => head = lane>>3; one fused pass.
// ---------------------------------------------------------------------------
__global__ __launch_bounds__(THREADS) void gat_main_kernel(
    const float* __restrict__ x,
    const float* __restrict__ embW, const float* __restrict__ embB,
    const float* __restrict__ lW,   const float* __restrict__ lb,
    const float* __restrict__ rW,   const float* __restrict__ rb,
    const float* __restrict__ att,  const float* __restrict__ gbias,
    const float* __restrict__ lng,  const float* __restrict__ lnb,
    const float* __restrict__ pW,   const float* __restrict__ pb,
    float* __restrict__ out)
{
    extern __shared__ float sm[];
    int*            s_rowptr = (int*)(sm + SM_FLOATS);
    float*          s_att    = (float*)(s_rowptr + 132);
    unsigned short* s_srcs   = (unsigned short*)(s_att + 256);

    const int b    = blockIdx.x;
    const int tid  = threadIdx.x;
    const int lane = tid & 31;
    const int warp = tid >> 5;

    // mma decomposition
    const int wm  = warp & 7;          // row group: rows 16*wm..+15
    const int wn  = warp >> 3;         // col group: cols 32*wn..+31
    const int gid = lane >> 2;
    const int tig = lane & 3;
    const int rw0 = 16 * wm + gid;     // fragment row (a0/c0); +8 for a1/c2
    const int cn0 = 32 * wn;

    float* attn_out = out + (size_t)B_ * L_ * C_;
    float* myattn   = attn_out + (size_t)b * C_ * C_;

    // --- load CSR + att into smem, zero this batch's attn-map region ---
    for (int i = tid; i <= C_; i += THREADS) s_rowptr[i] = g_rowptr[i];
    for (int i = tid; i < 256; i += THREADS) s_att[i] = att[i];
    for (int i = tid; i < EG_; i += THREADS) s_srcs[i] = g_srcs[i];
    {
        float4 z = make_float4(0.f, 0.f, 0.f, 0.f);
        float4* a4 = (float4*)myattn;
        for (int i = tid; i < C_ * C_ / 4; i += THREADS) a4[i] = z;
    }
    __syncthreads();

    // ================= Embedding: h = X_b^T(128x256) @ embW(256x128) + b ==============
    // A staged [k][m] (transpose via staging), B staged [k][n]; 16 chunks of k16.
    {
        const float* xb = x + (size_t)b * L_ * C_;
        float c[4][4];
        #pragma unroll
        for (int nt = 0; nt < 4; nt++)
            #pragma unroll
            for (int q = 0; q < 4; q++) c[nt][q] = 0.0f;

        float pA[2], pB[2];
        #pragma unroll
        for (int r = 0; r < 2; r++) {
            int i = tid + THREADS * r;
            int kk = i >> 7, cc = i & 127;
            pA[r] = xb[kk * C_ + cc];
            pB[r] = embW[kk * HID_ + cc];
        }
        for (int t = 0; t < 16; t++) {
            const int k0 = t * 16;
            #pragma unroll
            for (int r = 0; r < 2; r++) {
                int i = tid + THREADS * r;
                int kk = i >> 7, cc = i & 127;
                sm[SM_T0 + kk * TS + cc] = pA[r];
                sm[SM_T1 + kk * TS + cc] = pB[r];
            }
            __syncthreads();
            if (t < 15) {
                #pragma unroll
                for (int r = 0; r < 2; r++) {
                    int i = tid + THREADS * r;
                    int kk = i >> 7, cc = i & 127;
                    pA[r] = xb[(k0 + 16 + kk) * C_ + cc];
                    pB[r] = embW[(k0 + 16 + kk) * HID_ + cc];
                }
            }
            #pragma unroll
            for (int ks = 0; ks < 2; ks++) {
                const int kk = ks * 8;
                uint32_t ah[4], al[4];
                split_tf32(sm[SM_T0 + (kk + tig    ) * TS + rw0    ], ah[0], al[0]);
                split_tf32(sm[SM_T0 + (kk + tig    ) * TS + rw0 + 8], ah[1], al[1]);
                split_tf32(sm[SM_T0 + (kk + tig + 4) * TS + rw0    ], ah[2], al[2]);
                split_tf32(sm[SM_T0 + (kk + tig + 4) * TS + rw0 + 8], ah[3], al[3]);
                #pragma unroll
                for (int nt = 0; nt < 4; nt++) {
                    uint32_t bh0, bl0, bh1, bl1;
                    split_tf32(sm[SM_T1 + (kk + tig    ) * TS + cn0 + 8 * nt + gid], bh0, bl0);
                    split_tf32(sm[SM_T1 + (kk + tig + 4) * TS + cn0 + 8 * nt + gid], bh1, bl1);
                    mma8(c[nt], ah, bh0, bh1);
                    mma8(c[nt], ah, bl0, bl1);
                    mma8(c[nt], al, bh0, bh1);
                }
            }
            __syncthreads();   // single-buffered tiles: compute must finish before next store
        }
        #pragma unroll
        for (int nt = 0; nt < 4; nt++) {
            int col = cn0 + 8 * nt + 2 * tig;
            float2 bv = *(const float2*)&embB[col];
            *(float2*)&sm[SM_H + rw0 * HS + col] =
                make_float2(c[nt][0] + bv.x, c[nt][1] + bv.y);
            *(float2*)&sm[SM_H + (rw0 + 8) * HS + col] =
                make_float2(c[nt][2] + bv.x, c[nt][3] + bv.y);
        }
    }
    __syncthreads();

    // ================= Layers =========================================================
    for (int li = 0; li < 2; li++) {
        // --- xl = h @ Wl + bl ; xr = h @ Wr + br.
        //     A = h read in place [m][k]; B staged [k][n] ping-pong, 8 chunks of k16.
        for (int which = 0; which < 2; which++) {
            const float* W  = (which == 0 ? lW : rW) + (size_t)li * HID_ * HID_;
            const float* Bv = (which == 0 ? lb : rb) + li * HID_;
            const int dsto  = (which == 0) ? SM_XL : SM_XR;

            float c[4][4];
            #pragma unroll
            for (int nt = 0; nt < 4; nt++)
                #pragma unroll
                for (int q = 0; q < 4; q++) c[nt][q] = 0.0f;

            float pB[2];
            #pragma unroll
            for (int r = 0; r < 2; r++) {
                int i = tid + THREADS * r;
                int kk = i >> 7, cc = i & 127;
                pB[r] = W[kk * HID_ + cc];
            }
            for (int t = 0; t < 8; t++) {
                const int k0 = t * 16;
                const int buf = (t & 1) ? SM_T1 : SM_T0;
                #pragma unroll
                for (int r = 0; r < 2; r++) {
                    int i = tid + THREADS * r;
                    int kk = i >> 7, cc = i & 127;
                    sm[buf + kk * TS + cc] = pB[r];
                }
                __syncthreads();
                if (t < 7) {
                    #pragma unroll
                    for (int r = 0; r < 2; r++) {
                        int i = tid + THREADS * r;
                        int kk = i >> 7, cc = i & 127;
                        pB[r] = W[(k0 + 16 + kk) * HID_ + cc];
                    }
                }
                #pragma unroll
                for (int ks = 0; ks < 2; ks++) {
                    const int kk = ks * 8;
                    const int kg = k0 + kk;
                    uint32_t ah[4], al[4];
                    split_tf32(sm[SM_H + rw0 * HS + kg + tig], ah[0], al[0]);
                    split_tf32(sm[SM_H + (rw0 + 8) * HS + kg + tig], ah[1], al[1]);
                    split_tf32(sm[SM_H + rw0 * HS + kg + tig + 4], ah[2], al[2]);
                    split_tf32(sm[SM_H + (rw0 + 8) * HS + kg + tig + 4], ah[3], al[3]);
                    #pragma unroll
                    for (int nt = 0; nt < 4; nt++) {
                        uint32_t bh0, bl0, bh1, bl1;
                        split_tf32(sm[buf + (kk + tig    ) * TS + cn0 + 8 * nt + gid], bh0, bl0);
                        split_tf32(sm[buf + (kk + tig + 4) * TS + cn0 + 8 * nt + gid], bh1, bl1);
                        mma8(c[nt], ah, bh0, bh1);
                        mma8(c[nt], ah, bl0, bl1);
                        mma8(c[nt], al, bh0, bh1);
                    }
                }
            }
            #pragma unroll
            for (int nt = 0; nt < 4; nt++) {
                int col = cn0 + 8 * nt + 2 * tig;
                float2 bv = *(const float2*)&Bv[col];
                *(float2*)&sm[dsto + rw0 * HS + col] =
                    make_float2(c[nt][0] + bv.x, c[nt][1] + bv.y);
                *(float2*)&sm[dsto + (rw0 + 8) * HS + col] =
                    make_float2(c[nt][2] + bv.x, c[nt][3] + bv.y);
            }
            __syncthreads();
        }

        // --- fused edge phase (all 4 heads at once) + LayerNorm.
        //     Warp owns nodes {warp, warp+32, +64, +96}; no __syncthreads needed.
        {
            const float4 a4 = *(const float4*)&s_att[li * 128 + lane * 4];

            for (int n = warp; n < C_; n += 32) {
                const int beg = s_rowptr[n], end = s_rowptr[n + 1];
                const int deg = end - beg;
                int sreg[4];
                #pragma unroll
                for (int ch = 0; ch < 4; ch++) {
                    int t = beg + ch * 32 + lane;
                    sreg[ch] = (t < end) ? (int)s_srcs[t] : 0;
                }
                const float4 xr4 = *(const float4*)&sm[SM_XR + n * HS + lane * 4];

                float4 av = make_float4(0.f, 0.f, 0.f, 0.f);
                float psum = 0.0f;

                #pragma unroll
                for (int ch = 0; ch < 4; ch++) {
                    int base = ch * 32;
                    if (base >= deg) break;
                    int lim = min(32, deg - base);
                    #pragma unroll 8
                    for (int j = 0; j < lim; j++) {
                        int s = __shfl_sync(0xFFFFFFFFu, sreg[ch], j);
                        float4 xlv = *(const float4*)&sm[SM_XL + s * HS + lane * 4];
                        float vx = xlv.x + xr4.x; vx = fmaxf(vx, 0.2f * vx);
                        float vy = xlv.y + xr4.y; vy = fmaxf(vy, 0.2f * vy);
                        float vz = xlv.z + xr4.z; vz = fmaxf(vz, 0.2f * vz);
                        float vw = xlv.w + xr4.w; vw = fmaxf(vw, 0.2f * vw);
                        float t = vx * a4.x + vy * a4.y + vz * a4.z + vw * a4.w;
                        t += __shfl_xor_sync(0xFFFFFFFFu, t, 4);
                        t += __shfl_xor_sync(0xFFFFFFFFu, t, 2);
                        t += __shfl_xor_sync(0xFFFFFFFFu, t, 1);
                        float p = __expf(t);
                        psum += p;
                        av.x += p * xlv.x; av.y += p * xlv.y;
                        av.z += p * xlv.z; av.w += p * xlv.w;
                    }
                }
                const float inv = 1.0f / (psum + 1e-16f);
                av.x *= inv; av.y *= inv; av.z *= inv; av.w *= inv;
                *(float4*)&sm[SM_XR + n * HS + lane * 4] = av;

                if (li == 1) {
                    float aacc[4] = {0.f, 0.f, 0.f, 0.f};
                    #pragma unroll
                    for (int ch = 0; ch < 4; ch++) {
                        int base = ch * 32;
                        if (base >= deg) break;
                        int lim = min(32, deg - base);
                        #pragma unroll 8
                        for (int j = 0; j < lim; j++) {
                            int s = __shfl_sync(0xFFFFFFFFu, sreg[ch], j);
                            float4 xlv = *(const float4*)&sm[SM_XL + s * HS + lane * 4];
                            float vx = xlv.x + xr4.x; vx = fmaxf(vx, 0.2f * vx);
                            float vy = xlv.y + xr4.y; vy = fmaxf(vy, 0.2f * vy);
                            float vz = xlv.z + xr4.z; vz = fmaxf(vz, 0.2f * vz);
                            float vw = xlv.w + xr4.w; vw = fmaxf(vw, 0.2f * vw);
                            float t = vx * a4.x + vy * a4.y + vz * a4.z + vw * a4.w;
                            t += __shfl_xor_sync(0xFFFFFFFFu, t, 4);
                            t += __shfl_xor_sync(0xFFFFFFFFu, t, 2);
                            t += __shfl_xor_sync(0xFFFFFFFFu, t, 1);
                            float pin = __expf(t) * inv;
                            pin += __shfl_xor_sync(0xFFFFFFFFu, pin, 8);
                            pin += __shfl_xor_sync(0xFFFFFFFFu, pin, 16);
                            if (lane == j) aacc[ch] = pin;
                        }
                    }
                    #pragma unroll
                    for (int ch = 0; ch < 4; ch++) {
                        int t = beg + ch * 32 + lane;
                        if (t < end) atomicAdd(&myattn[n * C_ + sreg[ch]], aacc[ch] * 0.25f);
                    }
                }

                {
                    const float4 gb4 = *(const float4*)&gbias[li * HID_ + lane * 4];
                    float4 h4 = *(const float4*)&sm[SM_H + n * HS + lane * 4];
                    float v0 = av.x + gb4.x, v1 = av.y + gb4.y, v2 = av.z + gb4.z, v3 = av.w + gb4.w;
                    v0 = v0 > 0.f ? v0 : expm1f(v0);
                    v1 = v1 > 0.f ? v1 : expm1f(v1);
                    v2 = v2 > 0.f ? v2 : expm1f(v2);
                    v3 = v3 > 0.f ? v3 : expm1f(v3);
                    v0 += h4.x; v1 += h4.y; v2 += h4.z; v3 += h4.w;
                    float mu = warpSum(v0 + v1 + v2 + v3) * (1.0f / 128.0f);
                    float d0 = v0 - mu, d1 = v1 - mu, d2 = v2 - mu, d3 = v3 - mu;
                    float var = warpSum(d0 * d0 + d1 * d1 + d2 * d2 + d3 * d3) * (1.0f / 128.0f);
                    float rstd = rsqrtf(var + 1e-5f);
                    const float4 g4 = *(const float4*)&lng[li * HID_ + lane * 4];
                    const float4 b4 = *(const float4*)&lnb[li * HID_ + lane * 4];
                    float4 o;
                    o.x = d0 * rstd * g4.x + b4.x;
                    o.y = d1 * rstd * g4.y + b4.y;
                    o.z = d2 * rstd * g4.z + b4.z;
                    o.w = d3 * rstd * g4.w + b4.w;
                    *(float4*)&sm[SM_H + n * HS + lane * 4] = o;
                }
            }
        }
        __syncthreads();
    }

    // ================= Projection: out[b,l,c] = h[c,:] . pW[:,l] + pb[l] ==============
    // Two half-GEMMs (N=128 each); A = h in place, B staged ping-pong.
    for (int half = 0; half < 2; half++) {
        const int dsto = (half == 0) ? SM_XL : SM_XR;
        float c[4][4];
        #pragma unroll
        for (int nt = 0; nt < 4; nt++)
            #pragma unroll
            for (int q = 0; q < 4; q++) c[nt][q] = 0.0f;

        float pB[2];
        #pragma unroll
        for (int r = 0; r < 2; r++) {
            int i = tid + THREADS * r;
            int kk = i >> 7, cc = i & 127;
            pB[r] = pW[kk * L_ + half * 128 + cc];
        }
        for (int t = 0; t < 8; t++) {
            const int k0 = t * 16;
            const int buf = (t & 1) ? SM_T1 : SM_T0;
            #pragma unroll
            for (int r = 0; r < 2; r++) {
                int i = tid + THREADS * r;
                int kk = i >> 7, cc = i & 127;
                sm[buf + kk * TS + cc] = pB[r];
            }
            __syncthreads();
            if (t < 7) {
                #pragma unroll
                for (int r = 0; r < 2; r++) {
                    int i = tid + THREADS * r;
                    int kk = i >> 7, cc = i & 127;
                    pB[r] = pW[(k0 + 16 + kk) * L_ + half * 128 + cc];
                }
            }
            #pragma unroll
            for (int ks = 0; ks < 2; ks++) {
                const int kk = ks * 8;
                const int kg = k0 + kk;
                uint32_t ah[4], al[4];
                split_tf32(sm[SM_H + rw0 * HS + kg + tig], ah[0], al[0]);
                split_tf32(sm[SM_H + (rw0 + 8) * HS + kg + tig], ah[1], al[1]);
                split_tf32(sm[SM_H + rw0 * HS + kg + tig + 4], ah[2], al[2]);
                split_tf32(sm[SM_H + (rw0 + 8) * HS + kg + tig + 4], ah[3], al[3]);
                #pragma unroll
                for (int nt = 0; nt < 4; nt++) {
                    uint32_t bh0, bl0, bh1, bl1;
                    split_tf32(sm[buf + (kk + tig    ) * TS + cn0 + 8 * nt + gid], bh0, bl0);
                    split_tf32(sm[buf + (kk + tig + 4) * TS + cn0 + 8 * nt + gid], bh1, bl1);
                    mma8(c[nt], ah, bh0, bh1);
                    mma8(c[nt], ah, bl0, bl1);
                    mma8(c[nt], al, bh0, bh1);
                }
            }
        }
        // transposed store [l_local][c] into dsto for coalesced global writes
        #pragma unroll
        for (int nt = 0; nt < 4; nt++) {
            int col = cn0 + 8 * nt + 2 * tig;     // l_local
            float2 bv = *(const float2*)&pb[half * 128 + col];
            sm[dsto + (col    ) * HS + rw0    ] = c[nt][0] + bv.x;
            sm[dsto + (col + 1) * HS + rw0    ] = c[nt][1] + bv.y;
            sm[dsto + (col    ) * HS + rw0 + 8] = c[nt][2] + bv.x;
            sm[dsto + (col + 1) * HS + rw0 + 8] = c[nt][3] + bv.y;
        }
        __syncthreads();
    }
    for (int idx = tid; idx < 256 * C_; idx += THREADS) {
        int l = idx >> 7, cc = idx & 127;
        float v = (l < 128) ? sm[SM_XL + l * HS + cc] : sm[SM_XR + (l - 128) * HS + cc];
        out[(size_t)b * L_ * C_ + l * C_ + cc] = v;
    }
}

// ---------------------------------------------------------------------------
extern "C" void kernel_launch(void* const* d_in, const int* in_sizes, int n_in,
                              void* d_out, int out_size)
{
    const float* x    = (const float*)d_in[0];
    const int*   ei   = (const int*)  d_in[1];   // int32 or int64 (auto-detected)
    const float* embW = (const float*)d_in[2];
    const float* embB = (const float*)d_in[3];
    const float* lW   = (const float*)d_in[4];
    const float* lb   = (const float*)d_in[5];
    const float* rW   = (const float*)d_in[6];
    const float* rb   = (const float*)d_in[7];
    const float* att  = (const float*)d_in[8];
    const float* gb   = (const float*)d_in[9];
    const float* lng  = (const float*)d_in[10];
    const float* lnb  = (const float*)d_in[11];
    const float* pW   = (const float*)d_in[12];
    const float* pb   = (const float*)d_in[13];

    cudaFuncSetAttribute(gat_main_kernel,
                         cudaFuncAttributeMaxDynamicSharedMemorySize, SMEM_BYTES);

    prep_kernel<<<1, 256>>>(ei);
    gat_main_kernel<<<B_, THREADS, SMEM_BYTES>>>(x, embW, embB, lW, lb, rW, rb,
                                                 att, gb, lng, lnb, pW, pb,
                                                 (float*)d_out);
}